// round 4
// baseline (speedup 1.0000x reference)
#include <cuda_runtime.h>
#include <cstdint>

// LIF recurrence, per-warp double-buffered cp.async pipeline over tiles.
// x: [B*N, T] fp32, T=100 contiguous.
//   u_t = decay*u_{t-1} + x_t - o_{t-1}*VTH ; o_t = (u_t - VTH > 0) ? 1 : 0
//
// Each warp loops over 32-row tiles (12.8KB contiguous gmem span), warp-strided.
// Pipeline: prefetch tile k+1 (cp.async, own buffer) BEFORE scanning tile k,
// so every warp always has a full tile of loads in flight.

#define VTH 0.5f
#define T_STEPS 100
#define T_VEC (T_STEPS / 4)              // 25
#define ROWS_PER_TILE 32                 // per warp
#define TILE_FLOATS (ROWS_PER_TILE * T_STEPS)   // 3200 floats = 12800 B
#define WARPS_PER_BLOCK 4
#define BLOCK_THREADS (WARPS_PER_BLOCK * 32)
#define SMEM_BYTES (WARPS_PER_BLOCK * 2 * TILE_FLOATS * sizeof(float)) // 102400
#define GRID_BLOCKS 304                  // 2 per SM on 152 SMs

__device__ __forceinline__ void cp_async16(uint32_t smem_dst, const void* gmem_src) {
    asm volatile("cp.async.cg.shared.global [%0], [%1], 16;\n"
                 :: "r"(smem_dst), "l"(gmem_src));
}
__device__ __forceinline__ void cp_async_commit() {
    asm volatile("cp.async.commit_group;\n" ::: "memory");
}
__device__ __forceinline__ void cp_async_wait_1() {
    asm volatile("cp.async.wait_group 1;\n" ::: "memory");
}
__device__ __forceinline__ void cp_async_wait_0() {
    asm volatile("cp.async.wait_group 0;\n" ::: "memory");
}

#define LIF_STEP(u, o, xv)                      \
    do {                                        \
        u = fmaf(decay, u, xv);                 \
        u = fmaf(-VTH, o, u);                   \
        o = (u > VTH) ? 1.0f : 0.0f;            \
    } while (0)

__global__ void __launch_bounds__(BLOCK_THREADS) lif_kernel(
    const float* __restrict__ x,
    const float* __restrict__ decay_p,
    float* __restrict__ out,
    int n_neurons)
{
    extern __shared__ float smem[];

    const int warp = threadIdx.x >> 5;
    const int lane = threadIdx.x & 31;

    const int gwarp  = blockIdx.x * WARPS_PER_BLOCK + warp;
    const int nwarps = gridDim.x * WARPS_PER_BLOCK;
    const int ntiles = n_neurons / ROWS_PER_TILE;     // 8192

    const float decay = __ldg(decay_p);

    float* buf0 = smem + (size_t)warp * 2 * TILE_FLOATS;
    float* buf1 = buf0 + TILE_FLOATS;

    // Prologue: prefetch first tile.
    int t = gwarp;
    if (t < ntiles) {
        const float4* g = reinterpret_cast<const float4*>(
            x + (size_t)t * ROWS_PER_TILE * T_STEPS);
        uint32_t s = (uint32_t)__cvta_generic_to_shared(buf0);
#pragma unroll
        for (int i = 0; i < T_VEC; ++i) {
            int idx = lane + 32 * i;
            cp_async16(s + (uint32_t)idx * 16u, g + idx);
        }
        cp_async_commit();
    }

    int k = 0;
    for (; t < ntiles; t += nwarps, k ^= 1) {
        float* cur = k ? buf1 : buf0;
        float* nxt = k ? buf0 : buf1;

        // Prefetch next tile into the other buffer, then wait for current.
        int tn = t + nwarps;
        if (tn < ntiles) {
            const float4* g = reinterpret_cast<const float4*>(
                x + (size_t)tn * ROWS_PER_TILE * T_STEPS);
            uint32_t s = (uint32_t)__cvta_generic_to_shared(nxt);
#pragma unroll
            for (int i = 0; i < T_VEC; ++i) {
                int idx = lane + 32 * i;
                cp_async16(s + (uint32_t)idx * 16u, g + idx);
            }
            cp_async_commit();
            cp_async_wait_1();     // oldest group (tile t) done
        } else {
            cp_async_wait_0();
        }
        __syncwarp();

        // Scan own row (conflict-free LDS.128), spikes overwrite input in place.
        {
            float4* mrow = reinterpret_cast<float4*>(cur + (size_t)lane * T_STEPS);
            float u = 0.0f, o = 0.0f;
#pragma unroll
            for (int q = 0; q < T_VEC; ++q) {
                float4 a = mrow[q];
                float4 ov;
                LIF_STEP(u, o, a.x);  ov.x = o;
                LIF_STEP(u, o, a.y);  ov.y = o;
                LIF_STEP(u, o, a.z);  ov.z = o;
                LIF_STEP(u, o, a.w);  ov.w = o;
                mrow[q] = ov;
            }
        }
        __syncwarp();

        // Coalesced store of the spike tile.
        {
            const float4* c4 = reinterpret_cast<const float4*>(cur);
            float4* go = reinterpret_cast<float4*>(
                out + (size_t)t * ROWS_PER_TILE * T_STEPS);
#pragma unroll
            for (int i = 0; i < T_VEC; ++i) {
                int idx = lane + 32 * i;
                go[idx] = c4[idx];
            }
        }
        __syncwarp();   // buffer 'cur' safe to overwrite two iterations later
    }
}

extern "C" void kernel_launch(void* const* d_in, const int* in_sizes, int n_in,
                              void* d_out, int out_size)
{
    const float* x       = (const float*)d_in[0];
    const float* decay_p = (const float*)d_in[1];
    float*       out     = (float*)d_out;

    int n_neurons = in_sizes[0] / T_STEPS;   // 262144

    cudaFuncSetAttribute(lif_kernel,
                         cudaFuncAttributeMaxDynamicSharedMemorySize,
                         (int)SMEM_BYTES);

    lif_kernel<<<GRID_BLOCKS, BLOCK_THREADS, SMEM_BYTES>>>(x, decay_p, out, n_neurons);
}